// round 5
// baseline (speedup 1.0000x reference)
#include <cuda_runtime.h>
#include <cstdint>

#define MAXN 100000
#define MAXE 1600000
#define HDIM 128
#define FIN  9
#define GMAX 256
#define SCAN_B 256
#define MAXBLK 512   // max scan blocks (ceil(100000/256)=391)

typedef unsigned long long u64;

// -------- scratch (device symbols only; NEVER pass from host — GB300 ATS trap) ----
__device__ __align__(128) float g_dinv[MAXN];
__device__ __align__(128) float g_bufA[MAXN * HDIM];   // hw (post-GEMM, pre-agg)
__device__ __align__(128) float g_bufB[MAXN * HDIM];   // layer output (post-agg)
__device__ __align__(128) float g_xa[MAXN * FIN];      // aggregated input features
__device__ int   g_degc[MAXN];
__device__ int   g_rowstart[MAXN + 1];
__device__ int   g_cursor[MAXN];
__device__ int   g_bsum[MAXBLK];
__device__ int   g_boff[MAXBLK];
__device__ __align__(128) int2 g_cedge[MAXE];          // (src, norm-as-int) interleaved
__device__ int   g_lo[GMAX];
__device__ int   g_hi[GMAX];

// -------- f32x2 packed-FMA helpers (FFMA2 — only reachable via PTX) --------
__device__ __forceinline__ u64 pack2(float lo, float hi) {
    u64 r; asm("mov.b64 %0, {%1, %2};" : "=l"(r) : "f"(lo), "f"(hi)); return r;
}
__device__ __forceinline__ void ffma2(u64& d, u64 a, u64 b) {
    asm("fma.rn.f32x2 %0, %1, %2, %0;" : "+l"(d) : "l"(a), "l"(b));
}
__device__ __forceinline__ float2 unpack2(u64 v) {
    float2 f; asm("mov.b64 {%0, %1}, %2;" : "=f"(f.x), "=f"(f.y) : "l"(v)); return f;
}

// ======================= setup =======================
__global__ void k_clear(int n, int g) {
    int i = blockIdx.x * blockDim.x + threadIdx.x;
    if (i < n) g_degc[i] = 0;
    if (i < g) { g_lo[i] = 0; g_hi[i] = 0; }
}

__global__ void k_deg(const int* __restrict__ dst, int E) {
    int e = blockIdx.x * blockDim.x + threadIdx.x;
    if (e < E) atomicAdd(&g_degc[dst[e]], 1);
}

// block-local exclusive scan of degc + dinv computation (fused)
__global__ void k_scan1(int n) {
    __shared__ int sh[SCAN_B];
    int i = blockIdx.x * SCAN_B + threadIdx.x;
    int v = (i < n) ? g_degc[i] : 0;
    if (i < n) g_dinv[i] = rsqrtf((float)(v + 1));      // +1 self loop
    sh[threadIdx.x] = v;
    __syncthreads();
    for (int off = 1; off < SCAN_B; off <<= 1) {
        int t = (threadIdx.x >= (unsigned)off) ? sh[threadIdx.x - off] : 0;
        __syncthreads();
        sh[threadIdx.x] += t;
        __syncthreads();
    }
    if (i < n) g_rowstart[i] = sh[threadIdx.x] - v;     // local exclusive
    if (threadIdx.x == SCAN_B - 1) g_bsum[blockIdx.x] = sh[SCAN_B - 1];
}

// scan the block sums (single block, nb <= 512)
__global__ void k_scan2(int nb) {
    __shared__ int sh[MAXBLK];
    int v = (threadIdx.x < (unsigned)nb) ? g_bsum[threadIdx.x] : 0;
    sh[threadIdx.x] = v;
    __syncthreads();
    for (int off = 1; off < MAXBLK; off <<= 1) {
        int t = (threadIdx.x >= (unsigned)off) ? sh[threadIdx.x - off] : 0;
        __syncthreads();
        sh[threadIdx.x] += t;
        __syncthreads();
    }
    if (threadIdx.x < (unsigned)nb) g_boff[threadIdx.x] = sh[threadIdx.x] - v;
}

// finalize rowstart, init cursors
__global__ void k_scan3(int n, int E) {
    int i = blockIdx.x * blockDim.x + threadIdx.x;
    if (i < n) {
        int r = g_rowstart[i] + g_boff[i >> 8];
        g_rowstart[i] = r;
        g_cursor[i] = r;
    } else if (i == n) {
        g_rowstart[n] = E;
    }
}

// fill CSR: one interleaved 8B store per edge
__global__ void k_fill(const int* __restrict__ src, const int* __restrict__ dst, int E) {
    int e = blockIdx.x * blockDim.x + threadIdx.x;
    if (e >= E) return;
    int s = src[e], d = dst[e];
    int pos = atomicAdd(&g_cursor[d], 1);
    float nrm = g_dinv[s] * g_dinv[d];
    g_cedge[pos] = make_int2(s, __float_as_int(nrm));
}

// graph bounds via boundary detection (batch sorted)
__global__ void k_bounds(const int* __restrict__ batch, int n) {
    int i = blockIdx.x * blockDim.x + threadIdx.x;
    if (i >= n) return;
    int b = batch[i];
    if (i == 0) g_lo[b] = 0;
    else {
        int pb = batch[i - 1];
        if (pb != b) { g_lo[b] = i; g_hi[pb] = i; }
    }
    if (i == n - 1) g_hi[b] = n;
}

// ======================= layer 1: aggregate x (9 cols), then GEMM ============
// warp per node, lanes 0..8 carry one feature each
__global__ void k_aggx(const float* __restrict__ x, int n) {
    int w = (blockIdx.x * blockDim.x + threadIdx.x) >> 5;
    if (w >= n) return;
    int lane = threadIdx.x & 31;
    int rs = g_rowstart[w], re = g_rowstart[w + 1];
    float di = g_dinv[w];
    float acc = 0.f;
    if (lane < FIN) acc = x[w * FIN + lane] * di * di;
    for (int j = rs; j < re; j++) {
        int2 e = g_cedge[j];
        float wt = __int_as_float(e.y);
        if (lane < FIN) acc += x[e.x * FIN + lane] * wt;
    }
    if (lane < FIN) g_xa[w * FIN + lane] = acc;
}

// bufB = xa @ W1 + b1   (aggregation already applied)
__global__ void k_gemm_in(const float* __restrict__ W, const float* __restrict__ bias, int n) {
    __shared__ float xr[2][FIN];
    int slot = threadIdx.x / HDIM;
    int node = blockIdx.x * 2 + slot;
    int c = threadIdx.x % HDIM;
    if (node < n && c < FIN) xr[slot][c] = g_xa[node * FIN + c];
    __syncthreads();
    if (node >= n) return;
    float s = bias[c];
#pragma unroll
    for (int k = 0; k < FIN; k++) s += xr[slot][k] * W[k * HDIM + c];
    g_bufB[node * HDIM + c] = s;
}

// ======================= hidden GEMM: bufA = relu(bufB) @ W ==================
// 256 threads = 8 row-threads x 32 col-threads; tile 32 rows x 128 cols.
// 4x4 per thread, cols packed as 2x f32x2 — 8 FFMA2/k-step instead of 16 FFMA.
#define GR 32            // rows per block
#define RPAD 36          // rT row stride (16B-aligned, low-conflict)
__global__ void __launch_bounds__(256) k_gemm_h(const float* __restrict__ W, int n) {
    __shared__ float rT[HDIM * RPAD];   // rT[k][r] transposed inputs, 18.4KB
    int node0 = blockIdx.x * GR;
    for (int idx = threadIdx.x; idx < GR * HDIM; idx += 256) {
        int r = idx >> 7, c = idx & (HDIM - 1);
        float v = 0.f;
        if (node0 + r < n) v = fmaxf(g_bufB[(node0 + r) * HDIM + c], 0.f);
        rT[c * RPAD + r] = v;
    }
    __syncthreads();

    int ct = threadIdx.x & 31;   // 32 col-threads -> 128 cols
    int rt = threadIdx.x >> 5;   // 8  row-threads -> 32 rows
    u64 acc[4][2];
#pragma unroll
    for (int i = 0; i < 4; i++) { acc[i][0] = 0ull; acc[i][1] = 0ull; }

    const ulonglong2* __restrict__ Wp =
        reinterpret_cast<const ulonglong2*>(W) + ct;   // &W[k*128 + ct*4] as 2x u64

#pragma unroll 4
    for (int k = 0; k < HDIM; k++) {
        float4 a = *reinterpret_cast<const float4*>(&rT[k * RPAD + rt * 4]);  // uniform/bcast
        ulonglong2 wv = Wp[k * (HDIM / 4)];            // LDG.128, L1-resident
        u64 ax = pack2(a.x, a.x), ay = pack2(a.y, a.y);
        u64 az = pack2(a.z, a.z), aw = pack2(a.w, a.w);
        ffma2(acc[0][0], ax, wv.x); ffma2(acc[0][1], ax, wv.y);
        ffma2(acc[1][0], ay, wv.x); ffma2(acc[1][1], ay, wv.y);
        ffma2(acc[2][0], az, wv.x); ffma2(acc[2][1], az, wv.y);
        ffma2(acc[3][0], aw, wv.x); ffma2(acc[3][1], aw, wv.y);
    }
#pragma unroll
    for (int i = 0; i < 4; i++) {
        int node = node0 + rt * 4 + i;
        if (node < n) {
            float2 lo = unpack2(acc[i][0]), hi = unpack2(acc[i][1]);
            float4 o = make_float4(lo.x, lo.y, hi.x, hi.y);
            *reinterpret_cast<float4*>(&g_bufA[node * HDIM + ct * 4]) = o;
        }
    }
}

// ======================= hidden aggregate: bufB = Â bufA + bias ==============
// warp per node, each lane owns a float4 column slice; atomic-free gather.
// warp reads exactly one 512B row per edge (fully coalesced).
__global__ void k_gather_h(const float* __restrict__ bias, int n) {
    int w = (blockIdx.x * blockDim.x + threadIdx.x) >> 5;
    if (w >= n) return;
    int lane = threadIdx.x & 31;
    int q = lane * 4;
    int rs = g_rowstart[w], re = g_rowstart[w + 1];
    float di = g_dinv[w];

    float4 self = *reinterpret_cast<const float4*>(&g_bufA[w * HDIM + q]);
    float d2 = di * di;
    float4 acc = make_float4(self.x * d2, self.y * d2, self.z * d2, self.w * d2);

    int j = rs;
    for (; j + 3 < re; j += 4) {   // 4-way unroll for MLP
        int2 e0 = g_cedge[j],     e1 = g_cedge[j + 1];
        int2 e2 = g_cedge[j + 2], e3 = g_cedge[j + 3];
        float4 v0 = *reinterpret_cast<const float4*>(&g_bufA[e0.x * HDIM + q]);
        float4 v1 = *reinterpret_cast<const float4*>(&g_bufA[e1.x * HDIM + q]);
        float4 v2 = *reinterpret_cast<const float4*>(&g_bufA[e2.x * HDIM + q]);
        float4 v3 = *reinterpret_cast<const float4*>(&g_bufA[e3.x * HDIM + q]);
        float w0 = __int_as_float(e0.y), w1 = __int_as_float(e1.y);
        float w2 = __int_as_float(e2.y), w3 = __int_as_float(e3.y);
        acc.x += v0.x * w0 + v1.x * w1 + v2.x * w2 + v3.x * w3;
        acc.y += v0.y * w0 + v1.y * w1 + v2.y * w2 + v3.y * w3;
        acc.z += v0.z * w0 + v1.z * w1 + v2.z * w2 + v3.z * w3;
        acc.w += v0.w * w0 + v1.w * w1 + v2.w * w2 + v3.w * w3;
    }
    for (; j < re; j++) {
        int2 e = g_cedge[j];
        float wt = __int_as_float(e.y);
        float4 v = *reinterpret_cast<const float4*>(&g_bufA[e.x * HDIM + q]);
        acc.x += v.x * wt; acc.y += v.y * wt; acc.z += v.z * wt; acc.w += v.w * wt;
    }
    float4 b = __ldg(reinterpret_cast<const float4*>(&bias[q]));
    acc.x += b.x; acc.y += b.y; acc.z += b.z; acc.w += b.w;
    *reinterpret_cast<float4*>(&g_bufB[w * HDIM + q]) = acc;
}

// ======================= pool + final linear =======================
// 128 threads = 4 node-groups x 32 col-quads; coalesced float4 loads, MLP=4+.
__global__ void k_pool(const float* __restrict__ lin_w,
                       const float* __restrict__ lin_b,
                       float* __restrict__ out) {
    int g = blockIdx.x;
    int grp = threadIdx.x >> 5;     // 0..3
    int cq  = threadIdx.x & 31;     // col quad
    int q = cq * 4;
    int lo = g_lo[g], hi = g_hi[g];
    float4 acc = make_float4(0.f, 0.f, 0.f, 0.f);
    for (int node = lo + grp; node < hi; node += 4) {
        float4 v = *reinterpret_cast<const float4*>(&g_bufB[node * HDIM + q]);
        acc.x += v.x; acc.y += v.y; acc.z += v.z; acc.w += v.w;
    }
    __shared__ float4 sh[4][32];
    sh[grp][cq] = acc;
    __syncthreads();
    if (threadIdx.x < 32) {
        float4 a0 = sh[0][cq], a1 = sh[1][cq], a2 = sh[2][cq], a3 = sh[3][cq];
        float inv = 1.f / fmaxf((float)(hi - lo), 1.f);
        float4 lw4 = __ldg(reinterpret_cast<const float4*>(&lin_w[q]));
        float p = (a0.x + a1.x + a2.x + a3.x) * inv * lw4.x
                + (a0.y + a1.y + a2.y + a3.y) * inv * lw4.y
                + (a0.z + a1.z + a2.z + a3.z) * inv * lw4.z
                + (a0.w + a1.w + a2.w + a3.w) * inv * lw4.w;
#pragma unroll
        for (int off = 16; off > 0; off >>= 1)
            p += __shfl_down_sync(0xffffffffu, p, off);
        if (cq == 0) out[g] = p + lin_b[0];
    }
}

extern "C" void kernel_launch(void* const* d_in, const int* in_sizes, int n_in,
                              void* d_out, int out_size) {
    const float* x     = (const float*)d_in[0];
    const int*   ei    = (const int*)d_in[1];   // [2,E] int32
    const int*   batch = (const int*)d_in[2];   // [N]   int32
    const float* W1 = (const float*)d_in[3];
    const float* b1 = (const float*)d_in[4];
    const float* W2 = (const float*)d_in[5];
    const float* b2 = (const float*)d_in[6];
    const float* W3 = (const float*)d_in[7];
    const float* b3 = (const float*)d_in[8];
    const float* lw = (const float*)d_in[9];
    const float* lb = (const float*)d_in[10];
    float* out = (float*)d_out;

    int N = in_sizes[0] / FIN;
    int E = in_sizes[1] / 2;
    int G = out_size;

    const int* src = ei;
    const int* dst = ei + E;

    int nb  = (N + SCAN_B - 1) / SCAN_B;
    int eb  = (E + 255) / 256;
    int wb  = (N * 32 + 255) / 256;          // warp-per-node grids
    int gb  = (N + GR - 1) / GR;             // gemm_h blocks
    int inb = (N + 1) / 2;

    // ---- CSR build + bounds (once per launch, reused 3x) ----
    k_clear<<<nb, SCAN_B>>>(N, G);
    k_deg<<<eb, 256>>>(dst, E);
    k_scan1<<<nb, SCAN_B>>>(N);
    k_scan2<<<1, MAXBLK>>>(nb);
    k_scan3<<<(N + 256) / 256, 256>>>(N, E);
    k_fill<<<eb, 256>>>(src, dst, E);
    k_bounds<<<nb, SCAN_B>>>(batch, N);

    // ---- layer 1: (Â X) W1 + b1 ----
    k_aggx<<<wb, 256>>>(x, N);
    k_gemm_in<<<inb, 256>>>(W1, b1, N);
    // ---- layer 2 ----
    k_gemm_h<<<gb, 256>>>(W2, N);
    k_gather_h<<<wb, 256>>>(b2, N);
    // ---- layer 3 ----
    k_gemm_h<<<gb, 256>>>(W3, N);
    k_gather_h<<<wb, 256>>>(b3, N);

    // ---- pool + linear ----
    k_pool<<<G, HDIM>>>(lw, lb, out);
}

// round 6
// speedup vs baseline: 1.0959x; 1.0959x over previous
#include <cuda_runtime.h>
#include <cuda_bf16.h>
#include <cstdint>

#define MAXN 100000
#define MAXE 1600000
#define HDIM 128
#define FIN  9
#define GMAX 256
#define SCAN_B 256
#define MAXBLK 512   // max scan blocks (ceil(100000/256)=391)

// -------- scratch (device symbols only; NEVER pass from host — GB300 ATS trap) ----
__device__ __align__(128) float g_dinv[MAXN];
__device__ __align__(128) __nv_bfloat16 g_bufA16[MAXN * HDIM];  // pre-agg (bf16)
__device__ __align__(128) float g_bufB[MAXN * HDIM];            // layer output (fp32)
__device__ __align__(128) float g_xa[MAXN * FIN];               // aggregated input feats
__device__ int   g_degc[MAXN];
__device__ int   g_rowstart[MAXN + 1];
__device__ int   g_cursor[MAXN];
__device__ int   g_bsum[MAXBLK];
__device__ int   g_boff[MAXBLK];
__device__ __align__(128) int2 g_cedge[MAXE];   // (src, norm-as-int) interleaved
__device__ int   g_lo[GMAX];
__device__ int   g_hi[GMAX];

// ======================= setup =======================
__global__ void k_clear(int n, int g) {
    int i = blockIdx.x * blockDim.x + threadIdx.x;
    if (i < n) g_degc[i] = 0;
    if (i < g) { g_lo[i] = 0; g_hi[i] = 0; }
}

__global__ void k_deg(const int* __restrict__ dst, int E) {
    int e = blockIdx.x * blockDim.x + threadIdx.x;
    if (e < E) atomicAdd(&g_degc[dst[e]], 1);
}

// block-local exclusive scan of degc + dinv computation (fused)
__global__ void k_scan1(int n) {
    __shared__ int sh[SCAN_B];
    int i = blockIdx.x * SCAN_B + threadIdx.x;
    int v = (i < n) ? g_degc[i] : 0;
    if (i < n) g_dinv[i] = rsqrtf((float)(v + 1));      // +1 self loop
    sh[threadIdx.x] = v;
    __syncthreads();
    for (int off = 1; off < SCAN_B; off <<= 1) {
        int t = (threadIdx.x >= (unsigned)off) ? sh[threadIdx.x - off] : 0;
        __syncthreads();
        sh[threadIdx.x] += t;
        __syncthreads();
    }
    if (i < n) g_rowstart[i] = sh[threadIdx.x] - v;     // local exclusive
    if (threadIdx.x == SCAN_B - 1) g_bsum[blockIdx.x] = sh[SCAN_B - 1];
}

// scan the block sums (single block, nb <= 512)
__global__ void k_scan2(int nb) {
    __shared__ int sh[MAXBLK];
    int v = (threadIdx.x < (unsigned)nb) ? g_bsum[threadIdx.x] : 0;
    sh[threadIdx.x] = v;
    __syncthreads();
    for (int off = 1; off < MAXBLK; off <<= 1) {
        int t = (threadIdx.x >= (unsigned)off) ? sh[threadIdx.x - off] : 0;
        __syncthreads();
        sh[threadIdx.x] += t;
        __syncthreads();
    }
    if (threadIdx.x < (unsigned)nb) g_boff[threadIdx.x] = sh[threadIdx.x] - v;
}

// finalize rowstart + cursors; fused graph-bounds detection (batch sorted)
__global__ void k_scan3(const int* __restrict__ batch, int n, int E) {
    int i = blockIdx.x * blockDim.x + threadIdx.x;
    if (i < n) {
        int r = g_rowstart[i] + g_boff[i >> 8];
        g_rowstart[i] = r;
        g_cursor[i] = r;
        int b = batch[i];
        if (i == 0) g_lo[b] = 0;
        else {
            int pb = batch[i - 1];
            if (pb != b) { g_lo[b] = i; g_hi[pb] = i; }
        }
        if (i == n - 1) g_hi[b] = n;
    } else if (i == n) {
        g_rowstart[n] = E;
    }
}

// fill CSR: one interleaved 8B store per edge
__global__ void k_fill(const int* __restrict__ src, const int* __restrict__ dst, int E) {
    int e = blockIdx.x * blockDim.x + threadIdx.x;
    if (e >= E) return;
    int s = src[e], d = dst[e];
    int pos = atomicAdd(&g_cursor[d], 1);
    float nrm = g_dinv[s] * g_dinv[d];
    g_cedge[pos] = make_int2(s, __float_as_int(nrm));
}

// ======================= layer 1: aggregate x (9 cols), then GEMM ============
// warp per node, lanes 0..8 carry one feature each
__global__ void k_aggx(const float* __restrict__ x, int n) {
    int w = (blockIdx.x * blockDim.x + threadIdx.x) >> 5;
    if (w >= n) return;
    int lane = threadIdx.x & 31;
    int rs = g_rowstart[w], re = g_rowstart[w + 1];
    float di = g_dinv[w];
    float acc = 0.f;
    if (lane < FIN) acc = x[w * FIN + lane] * di * di;
    for (int j = rs; j < re; j++) {
        int2 e = g_cedge[j];
        float wt = __int_as_float(e.y);
        if (lane < FIN) acc += x[e.x * FIN + lane] * wt;
    }
    if (lane < FIN) g_xa[w * FIN + lane] = acc;
}

// bufB = xa @ W1 + b1   (aggregation already applied)
__global__ void k_gemm_in(const float* __restrict__ W, const float* __restrict__ bias, int n) {
    __shared__ float xr[2][FIN];
    int slot = threadIdx.x / HDIM;
    int node = blockIdx.x * 2 + slot;
    int c = threadIdx.x % HDIM;
    if (node < n && c < FIN) xr[slot][c] = g_xa[node * FIN + c];
    __syncthreads();
    if (node >= n) return;
    float s = bias[c];
#pragma unroll
    for (int k = 0; k < FIN; k++) s += xr[slot][k] * W[k * HDIM + c];
    g_bufB[node * HDIM + c] = s;
}

// ======================= hidden GEMM: bufA16 = bf16(relu(bufB) @ W) ==========
// 256 threads = 8 row-threads x 32 col-threads; tile 32 rows x 128 cols.
// R4-proven plain-FFMA 4x4 tile; epilogue converts to bf16 (halves store+gather bytes).
#define GR 32            // rows per block
#define RPAD 36          // rT row stride (16B-aligned, low-conflict)
__global__ void __launch_bounds__(256) k_gemm_h(const float* __restrict__ W, int n) {
    __shared__ float rT[HDIM * RPAD];   // rT[k][r] transposed inputs, 18.4KB
    int node0 = blockIdx.x * GR;
    for (int idx = threadIdx.x; idx < GR * HDIM; idx += 256) {
        int r = idx >> 7, c = idx & (HDIM - 1);
        float v = 0.f;
        if (node0 + r < n) v = fmaxf(g_bufB[(node0 + r) * HDIM + c], 0.f);
        rT[c * RPAD + r] = v;
    }
    __syncthreads();

    int ct = threadIdx.x & 31;   // 32 col-threads -> 128 cols
    int rt = threadIdx.x >> 5;   // 8  row-threads -> 32 rows
    float acc[4][4];
#pragma unroll
    for (int i = 0; i < 4; i++)
#pragma unroll
        for (int j = 0; j < 4; j++) acc[i][j] = 0.f;

#pragma unroll 2
    for (int k = 0; k < HDIM; k++) {
        float4 a = *reinterpret_cast<const float4*>(&rT[k * RPAD + rt * 4]);  // broadcast
        float4 wv = __ldg(reinterpret_cast<const float4*>(&W[k * HDIM + ct * 4]));
        acc[0][0] += a.x * wv.x; acc[0][1] += a.x * wv.y; acc[0][2] += a.x * wv.z; acc[0][3] += a.x * wv.w;
        acc[1][0] += a.y * wv.x; acc[1][1] += a.y * wv.y; acc[1][2] += a.y * wv.z; acc[1][3] += a.y * wv.w;
        acc[2][0] += a.z * wv.x; acc[2][1] += a.z * wv.y; acc[2][2] += a.z * wv.z; acc[2][3] += a.z * wv.w;
        acc[3][0] += a.w * wv.x; acc[3][1] += a.w * wv.y; acc[3][2] += a.w * wv.z; acc[3][3] += a.w * wv.w;
    }
#pragma unroll
    for (int i = 0; i < 4; i++) {
        int node = node0 + rt * 4 + i;
        if (node < n) {
            __nv_bfloat162 p0 = __floats2bfloat162_rn(acc[i][0], acc[i][1]);
            __nv_bfloat162 p1 = __floats2bfloat162_rn(acc[i][2], acc[i][3]);
            uint2 o;
            o.x = *reinterpret_cast<unsigned*>(&p0);
            o.y = *reinterpret_cast<unsigned*>(&p1);
            *reinterpret_cast<uint2*>(&g_bufA16[node * HDIM + ct * 4]) = o;
        }
    }
}

// ======================= hidden aggregate: bufB = Â bufA16 + bias ============
// warp per node, lane owns 4 bf16 cols (8B load, 256B/warp-row); fp32 accumulate.
__device__ __forceinline__ float4 ld_row4(int node, int q) {
    uint2 raw = *reinterpret_cast<const uint2*>(&g_bufA16[node * HDIM + q]);
    __nv_bfloat162 p0 = *reinterpret_cast<__nv_bfloat162*>(&raw.x);
    __nv_bfloat162 p1 = *reinterpret_cast<__nv_bfloat162*>(&raw.y);
    float2 f0 = __bfloat1622float2(p0);
    float2 f1 = __bfloat1622float2(p1);
    return make_float4(f0.x, f0.y, f1.x, f1.y);
}

__global__ void k_gather_h(const float* __restrict__ bias, int n) {
    int w = (blockIdx.x * blockDim.x + threadIdx.x) >> 5;
    if (w >= n) return;
    int lane = threadIdx.x & 31;
    int q = lane * 4;
    int rs = g_rowstart[w], re = g_rowstart[w + 1];
    float di = g_dinv[w];

    float4 self = ld_row4(w, q);
    float d2 = di * di;
    float4 acc = make_float4(self.x * d2, self.y * d2, self.z * d2, self.w * d2);

    int j = rs;
    for (; j + 3 < re; j += 4) {   // 4-way unroll for MLP
        int2 e0 = g_cedge[j],     e1 = g_cedge[j + 1];
        int2 e2 = g_cedge[j + 2], e3 = g_cedge[j + 3];
        float4 v0 = ld_row4(e0.x, q);
        float4 v1 = ld_row4(e1.x, q);
        float4 v2 = ld_row4(e2.x, q);
        float4 v3 = ld_row4(e3.x, q);
        float w0 = __int_as_float(e0.y), w1 = __int_as_float(e1.y);
        float w2 = __int_as_float(e2.y), w3 = __int_as_float(e3.y);
        acc.x += v0.x * w0 + v1.x * w1 + v2.x * w2 + v3.x * w3;
        acc.y += v0.y * w0 + v1.y * w1 + v2.y * w2 + v3.y * w3;
        acc.z += v0.z * w0 + v1.z * w1 + v2.z * w2 + v3.z * w3;
        acc.w += v0.w * w0 + v1.w * w1 + v2.w * w2 + v3.w * w3;
    }
    for (; j < re; j++) {
        int2 e = g_cedge[j];
        float wt = __int_as_float(e.y);
        float4 v = ld_row4(e.x, q);
        acc.x += v.x * wt; acc.y += v.y * wt; acc.z += v.z * wt; acc.w += v.w * wt;
    }
    float4 b = __ldg(reinterpret_cast<const float4*>(&bias[q]));
    acc.x += b.x; acc.y += b.y; acc.z += b.z; acc.w += b.w;
    *reinterpret_cast<float4*>(&g_bufB[w * HDIM + q]) = acc;
}

// ======================= pool + final linear =======================
// 128 threads = 4 node-groups x 32 col-quads; coalesced float4 loads.
__global__ void k_pool(const float* __restrict__ lin_w,
                       const float* __restrict__ lin_b,
                       float* __restrict__ out) {
    int g = blockIdx.x;
    int grp = threadIdx.x >> 5;     // 0..3
    int cq  = threadIdx.x & 31;     // col quad
    int q = cq * 4;
    int lo = g_lo[g], hi = g_hi[g];
    float4 acc = make_float4(0.f, 0.f, 0.f, 0.f);
    for (int node = lo + grp; node < hi; node += 4) {
        float4 v = *reinterpret_cast<const float4*>(&g_bufB[node * HDIM + q]);
        acc.x += v.x; acc.y += v.y; acc.z += v.z; acc.w += v.w;
    }
    __shared__ float4 sh[4][32];
    sh[grp][cq] = acc;
    __syncthreads();
    if (threadIdx.x < 32) {
        float4 a0 = sh[0][cq], a1 = sh[1][cq], a2 = sh[2][cq], a3 = sh[3][cq];
        float inv = 1.f / fmaxf((float)(hi - lo), 1.f);
        float4 lw4 = __ldg(reinterpret_cast<const float4*>(&lin_w[q]));
        float p = (a0.x + a1.x + a2.x + a3.x) * inv * lw4.x
                + (a0.y + a1.y + a2.y + a3.y) * inv * lw4.y
                + (a0.z + a1.z + a2.z + a3.z) * inv * lw4.z
                + (a0.w + a1.w + a2.w + a3.w) * inv * lw4.w;
#pragma unroll
        for (int off = 16; off > 0; off >>= 1)
            p += __shfl_down_sync(0xffffffffu, p, off);
        if (cq == 0) out[g] = p + lin_b[0];
    }
}

extern "C" void kernel_launch(void* const* d_in, const int* in_sizes, int n_in,
                              void* d_out, int out_size) {
    const float* x     = (const float*)d_in[0];
    const int*   ei    = (const int*)d_in[1];   // [2,E] int32
    const int*   batch = (const int*)d_in[2];   // [N]   int32
    const float* W1 = (const float*)d_in[3];
    const float* b1 = (const float*)d_in[4];
    const float* W2 = (const float*)d_in[5];
    const float* b2 = (const float*)d_in[6];
    const float* W3 = (const float*)d_in[7];
    const float* b3 = (const float*)d_in[8];
    const float* lw = (const float*)d_in[9];
    const float* lb = (const float*)d_in[10];
    float* out = (float*)d_out;

    int N = in_sizes[0] / FIN;
    int E = in_sizes[1] / 2;
    int G = out_size;

    const int* src = ei;
    const int* dst = ei + E;

    int nb  = (N + SCAN_B - 1) / SCAN_B;
    int eb  = (E + 255) / 256;
    int wb  = (N * 32 + 255) / 256;          // warp-per-node grids
    int gb  = (N + GR - 1) / GR;             // gemm_h blocks
    int inb = (N + 1) / 2;

    // ---- CSR build + bounds (once per launch, reused 3x) ----
    k_clear<<<nb, SCAN_B>>>(N, G);
    k_deg<<<eb, 256>>>(dst, E);
    k_scan1<<<nb, SCAN_B>>>(N);
    k_scan2<<<1, MAXBLK>>>(nb);
    k_scan3<<<(N + 256) / 256, 256>>>(batch, N, E);
    k_fill<<<eb, 256>>>(src, dst, E);

    // ---- layer 1: (Â X) W1 + b1 ----
    k_aggx<<<wb, 256>>>(x, N);
    k_gemm_in<<<inb, 256>>>(W1, b1, N);
    // ---- layer 2 ----
    k_gemm_h<<<gb, 256>>>(W2, N);
    k_gather_h<<<wb, 256>>>(b2, N);
    // ---- layer 3 ----
    k_gemm_h<<<gb, 256>>>(W3, N);
    k_gather_h<<<wb, 256>>>(b3, N);

    // ---- pool + linear ----
    k_pool<<<G, HDIM>>>(lw, lb, out);
}

// round 8
// speedup vs baseline: 1.1261x; 1.0275x over previous
#include <cuda_runtime.h>
#include <cuda_bf16.h>
#include <cstdint>

#define MAXN 100000
#define MAXE 1600000
#define HDIM 128
#define FIN  9
#define GMAX 256
#define SCAN_B 256
#define MAXBLK 512
#define KC   64                 // k per staging phase
#define AST  68                 // padded smem stride (68 mod 32 == 4 -> conflict-free frags)
#define GEMM_SMEM (4 * 128 * AST * 4)   // A_hi, A_lo, W_hi, W_lo = 139264 B

// -------- scratch (device symbols only; NEVER pass from host — GB300 ATS trap) ----
__device__ __align__(128) float g_dinv[MAXN];
__device__ __align__(128) __nv_bfloat16 g_bufA16[MAXN * HDIM];  // pre-agg (bf16)
__device__ __align__(128) float g_bufB[MAXN * HDIM];            // layer output (fp32)
__device__ __align__(128) float g_xa[MAXN * FIN];
__device__ int   g_degc[MAXN];
__device__ int   g_rowstart[MAXN + 1];
__device__ int   g_cursor[MAXN];
__device__ int   g_bsum[MAXBLK];
__device__ int   g_boff[MAXBLK];
__device__ __align__(128) int2 g_cedge[MAXE];   // (src, norm-as-int)
__device__ int   g_lo[GMAX];
__device__ int   g_hi[GMAX];

__device__ __forceinline__ unsigned f2tf32(float f) {
    unsigned u;
    asm("cvt.rna.tf32.f32 %0, %1;" : "=r"(u) : "f"(f));
    return u;
}
// split f into tf32 hi + tf32 lo (Dekker residual, exact subtraction)
__device__ __forceinline__ void tf32split(float f, unsigned& hi, unsigned& lo) {
    hi = f2tf32(f);
    float hif = __uint_as_float(hi);
    lo = f2tf32(f - hif);
}

// ======================= setup =======================
__global__ void k_clear(int n, int g) {
    int i = blockIdx.x * blockDim.x + threadIdx.x;
    if (i < n) g_degc[i] = 0;
    if (i < g) { g_lo[i] = 0; g_hi[i] = 0; }
}

__global__ void k_deg(const int* __restrict__ dst, int E) {
    int e = blockIdx.x * blockDim.x + threadIdx.x;
    if (e < E) atomicAdd(&g_degc[dst[e]], 1);
}

__global__ void k_scan1(int n) {
    __shared__ int sh[SCAN_B];
    int i = blockIdx.x * SCAN_B + threadIdx.x;
    int v = (i < n) ? g_degc[i] : 0;
    if (i < n) g_dinv[i] = rsqrtf((float)(v + 1));
    sh[threadIdx.x] = v;
    __syncthreads();
    for (int off = 1; off < SCAN_B; off <<= 1) {
        int t = (threadIdx.x >= (unsigned)off) ? sh[threadIdx.x - off] : 0;
        __syncthreads();
        sh[threadIdx.x] += t;
        __syncthreads();
    }
    if (i < n) g_rowstart[i] = sh[threadIdx.x] - v;
    if (threadIdx.x == SCAN_B - 1) g_bsum[blockIdx.x] = sh[SCAN_B - 1];
}

__global__ void k_scan2(int nb) {
    __shared__ int sh[MAXBLK];
    int v = (threadIdx.x < (unsigned)nb) ? g_bsum[threadIdx.x] : 0;
    sh[threadIdx.x] = v;
    __syncthreads();
    for (int off = 1; off < MAXBLK; off <<= 1) {
        int t = (threadIdx.x >= (unsigned)off) ? sh[threadIdx.x - off] : 0;
        __syncthreads();
        sh[threadIdx.x] += t;
        __syncthreads();
    }
    if (threadIdx.x < (unsigned)nb) g_boff[threadIdx.x] = sh[threadIdx.x] - v;
}

__global__ void k_scan3(const int* __restrict__ batch, int n, int E) {
    int i = blockIdx.x * blockDim.x + threadIdx.x;
    if (i < n) {
        int r = g_rowstart[i] + g_boff[i >> 8];
        g_rowstart[i] = r;
        g_cursor[i] = r;
        int b = batch[i];
        if (i == 0) g_lo[b] = 0;
        else {
            int pb = batch[i - 1];
            if (pb != b) { g_lo[b] = i; g_hi[pb] = i; }
        }
        if (i == n - 1) g_hi[b] = n;
    } else if (i == n) {
        g_rowstart[n] = E;
    }
}

__global__ void k_fill(const int* __restrict__ src, const int* __restrict__ dst, int E) {
    int e = blockIdx.x * blockDim.x + threadIdx.x;
    if (e >= E) return;
    int s = src[e], d = dst[e];
    int pos = atomicAdd(&g_cursor[d], 1);
    float nrm = g_dinv[s] * g_dinv[d];
    g_cedge[pos] = make_int2(s, __float_as_int(nrm));
}

// ======================= layer 1 =======================
__global__ void k_aggx(const float* __restrict__ x, int n) {
    int w = (blockIdx.x * blockDim.x + threadIdx.x) >> 5;
    if (w >= n) return;
    int lane = threadIdx.x & 31;
    int rs = g_rowstart[w], re = g_rowstart[w + 1];
    float di = g_dinv[w];
    float acc = 0.f;
    if (lane < FIN) acc = x[w * FIN + lane] * di * di;
    for (int j = rs; j < re; j++) {
        int2 e = g_cedge[j];
        float wt = __int_as_float(e.y);
        if (lane < FIN) acc += x[e.x * FIN + lane] * wt;
    }
    if (lane < FIN) g_xa[w * FIN + lane] = acc;
}

__global__ void k_gemm_in(const float* __restrict__ W, const float* __restrict__ bias, int n) {
    __shared__ float xr[2][FIN];
    int slot = threadIdx.x / HDIM;
    int node = blockIdx.x * 2 + slot;
    int c = threadIdx.x % HDIM;
    if (node < n && c < FIN) xr[slot][c] = g_xa[node * FIN + c];
    __syncthreads();
    if (node >= n) return;
    float s = bias[c];
#pragma unroll
    for (int k = 0; k < FIN; k++) s += xr[slot][k] * W[k * HDIM + c];
    g_bufB[node * HDIM + c] = s;
}

// =============== hidden GEMM: 3xTF32 warp-MMA (fp32-accurate) ================
// CTA tile 128x128; K processed in 2 phases of 64 (smem re-staged, accum persists).
// A = relu(g_bufB) split hi/lo; B = W^T split hi/lo. d += hi*hi + hi*lo + lo*hi.
// Output bf16 -> g_bufA16 (feeds gather).
__global__ void __launch_bounds__(256) k_gemm_mma(const float* __restrict__ W, int n) {
    extern __shared__ unsigned smu[];
    unsigned* sAhi = smu;
    unsigned* sAlo = smu + 128 * AST;
    unsigned* sWhi = smu + 2 * 128 * AST;
    unsigned* sWlo = smu + 3 * 128 * AST;
    int tid = threadIdx.x;
    int node0 = blockIdx.x * 128;

    int wid = tid >> 5, lane = tid & 31;
    int m0 = wid * 16;
    int lr = lane >> 2;      // 0..7
    int lc = lane & 3;       // 0..3

    float d[16][4];
#pragma unroll
    for (int t = 0; t < 16; t++)
#pragma unroll
        for (int j = 0; j < 4; j++) d[t][j] = 0.f;

    for (int p = 0; p < 2; p++) {
        int k0 = p * KC;
        if (p) __syncthreads();   // protect smem reuse
        // stage A chunk: 128 rows x 64 k (relu + split)
        for (int idx = tid; idx < 128 * KC; idx += 256) {
            int r = idx >> 6, c = idx & (KC - 1);
            float v = 0.f;
            if (node0 + r < n) v = fmaxf(g_bufB[(node0 + r) * HDIM + k0 + c], 0.f);
            unsigned hi, lo; tf32split(v, hi, lo);
            sAhi[r * AST + c] = hi;
            sAlo[r * AST + c] = lo;
        }
        // stage W^T chunk: sW[nn][kl] = split(W[k0+kl][nn])
        for (int idx = tid; idx < KC * 128; idx += 256) {
            int kl = idx >> 7, nn = idx & 127;
            float v = __ldg(&W[(k0 + kl) * HDIM + nn]);
            unsigned hi, lo; tf32split(v, hi, lo);
            sWhi[nn * AST + kl] = hi;
            sWlo[nn * AST + kl] = lo;
        }
        __syncthreads();

        const unsigned* pah = &sAhi[(m0 + lr) * AST + lc];
        const unsigned* pal = &sAlo[(m0 + lr) * AST + lc];

#pragma unroll
        for (int kc = 0; kc < KC / 8; kc++) {
            int kb = kc * 8;
            unsigned ah0 = pah[kb],           ah1 = pah[8 * AST + kb];
            unsigned ah2 = pah[kb + 4],       ah3 = pah[8 * AST + kb + 4];
            unsigned al0 = pal[kb],           al1 = pal[8 * AST + kb];
            unsigned al2 = pal[kb + 4],       al3 = pal[8 * AST + kb + 4];
#pragma unroll
            for (int t = 0; t < 16; t++) {
                const unsigned* pbh = &sWhi[(t * 8 + lr) * AST + kb + lc];
                const unsigned* pbl = &sWlo[(t * 8 + lr) * AST + kb + lc];
                unsigned bh0 = pbh[0], bh1 = pbh[4];
                unsigned bl0 = pbl[0], bl1 = pbl[4];
                asm volatile(
                    "mma.sync.aligned.m16n8k8.row.col.f32.tf32.tf32.f32 "
                    "{%0,%1,%2,%3}, {%4,%5,%6,%7}, {%8,%9}, {%0,%1,%2,%3};"
                    : "+f"(d[t][0]), "+f"(d[t][1]), "+f"(d[t][2]), "+f"(d[t][3])
                    : "r"(ah0), "r"(ah1), "r"(ah2), "r"(ah3), "r"(bh0), "r"(bh1));
                asm volatile(
                    "mma.sync.aligned.m16n8k8.row.col.f32.tf32.tf32.f32 "
                    "{%0,%1,%2,%3}, {%4,%5,%6,%7}, {%8,%9}, {%0,%1,%2,%3};"
                    : "+f"(d[t][0]), "+f"(d[t][1]), "+f"(d[t][2]), "+f"(d[t][3])
                    : "r"(ah0), "r"(ah1), "r"(ah2), "r"(ah3), "r"(bl0), "r"(bl1));
                asm volatile(
                    "mma.sync.aligned.m16n8k8.row.col.f32.tf32.tf32.f32 "
                    "{%0,%1,%2,%3}, {%4,%5,%6,%7}, {%8,%9}, {%0,%1,%2,%3};"
                    : "+f"(d[t][0]), "+f"(d[t][1]), "+f"(d[t][2]), "+f"(d[t][3])
                    : "r"(al0), "r"(al1), "r"(al2), "r"(al3), "r"(bh0), "r"(bh1));
            }
        }
    }

    // epilogue: bf16 pairs. D rows m0+lr (+8), cols t*8 + 2*lc (+1).
    int row0 = node0 + m0 + lr;
    int row1 = row0 + 8;
#pragma unroll
    for (int t = 0; t < 16; t++) {
        int col = t * 8 + lc * 2;
        if (row0 < n) {
            __nv_bfloat162 pp = __floats2bfloat162_rn(d[t][0], d[t][1]);
            *reinterpret_cast<unsigned*>(&g_bufA16[row0 * HDIM + col]) =
                *reinterpret_cast<unsigned*>(&pp);
        }
        if (row1 < n) {
            __nv_bfloat162 pp = __floats2bfloat162_rn(d[t][2], d[t][3]);
            *reinterpret_cast<unsigned*>(&g_bufA16[row1 * HDIM + col]) =
                *reinterpret_cast<unsigned*>(&pp);
        }
    }
}

// ======================= hidden aggregate =======================
__device__ __forceinline__ float4 ld_row4(int node, int q) {
    uint2 raw = *reinterpret_cast<const uint2*>(&g_bufA16[node * HDIM + q]);
    __nv_bfloat162 p0 = *reinterpret_cast<__nv_bfloat162*>(&raw.x);
    __nv_bfloat162 p1 = *reinterpret_cast<__nv_bfloat162*>(&raw.y);
    float2 f0 = __bfloat1622float2(p0);
    float2 f1 = __bfloat1622float2(p1);
    return make_float4(f0.x, f0.y, f1.x, f1.y);
}

__global__ void k_gather_h(const float* __restrict__ bias, int n) {
    int w = (blockIdx.x * blockDim.x + threadIdx.x) >> 5;
    if (w >= n) return;
    int lane = threadIdx.x & 31;
    int q = lane * 4;
    int rs = g_rowstart[w], re = g_rowstart[w + 1];
    float di = g_dinv[w];

    float4 self = ld_row4(w, q);
    float d2 = di * di;
    float4 acc = make_float4(self.x * d2, self.y * d2, self.z * d2, self.w * d2);

    int j = rs;
    for (; j + 3 < re; j += 4) {
        int2 e0 = g_cedge[j],     e1 = g_cedge[j + 1];
        int2 e2 = g_cedge[j + 2], e3 = g_cedge[j + 3];
        float4 v0 = ld_row4(e0.x, q);
        float4 v1 = ld_row4(e1.x, q);
        float4 v2 = ld_row4(e2.x, q);
        float4 v3 = ld_row4(e3.x, q);
        float w0 = __int_as_float(e0.y), w1 = __int_as_float(e1.y);
        float w2 = __int_as_float(e2.y), w3 = __int_as_float(e3.y);
        acc.x += v0.x * w0 + v1.x * w1 + v2.x * w2 + v3.x * w3;
        acc.y += v0.y * w0 + v1.y * w1 + v2.y * w2 + v3.y * w3;
        acc.z += v0.z * w0 + v1.z * w1 + v2.z * w2 + v3.z * w3;
        acc.w += v0.w * w0 + v1.w * w1 + v2.w * w2 + v3.w * w3;
    }
    for (; j < re; j++) {
        int2 e = g_cedge[j];
        float wt = __int_as_float(e.y);
        float4 v = ld_row4(e.x, q);
        acc.x += v.x * wt; acc.y += v.y * wt; acc.z += v.z * wt; acc.w += v.w * wt;
    }
    float4 b = __ldg(reinterpret_cast<const float4*>(&bias[q]));
    acc.x += b.x; acc.y += b.y; acc.z += b.z; acc.w += b.w;
    *reinterpret_cast<float4*>(&g_bufB[w * HDIM + q]) = acc;
}

// ======================= pool + final linear =======================
__global__ void k_pool(const float* __restrict__ lin_w,
                       const float* __restrict__ lin_b,
                       float* __restrict__ out) {
    int g = blockIdx.x;
    int grp = threadIdx.x >> 5;
    int cq  = threadIdx.x & 31;
    int q = cq * 4;
    int lo = g_lo[g], hi = g_hi[g];
    float4 acc = make_float4(0.f, 0.f, 0.f, 0.f);
    for (int node = lo + grp; node < hi; node += 4) {
        float4 v = *reinterpret_cast<const float4*>(&g_bufB[node * HDIM + q]);
        acc.x += v.x; acc.y += v.y; acc.z += v.z; acc.w += v.w;
    }
    __shared__ float4 sh[4][32];
    sh[grp][cq] = acc;
    __syncthreads();
    if (threadIdx.x < 32) {
        float4 a0 = sh[0][cq], a1 = sh[1][cq], a2 = sh[2][cq], a3 = sh[3][cq];
        float inv = 1.f / fmaxf((float)(hi - lo), 1.f);
        float4 lw4 = __ldg(reinterpret_cast<const float4*>(&lin_w[q]));
        float p = (a0.x + a1.x + a2.x + a3.x) * inv * lw4.x
                + (a0.y + a1.y + a2.y + a3.y) * inv * lw4.y
                + (a0.z + a1.z + a2.z + a3.z) * inv * lw4.z
                + (a0.w + a1.w + a2.w + a3.w) * inv * lw4.w;
#pragma unroll
        for (int off = 16; off > 0; off >>= 1)
            p += __shfl_down_sync(0xffffffffu, p, off);
        if (cq == 0) out[g] = p + lin_b[0];
    }
}

extern "C" void kernel_launch(void* const* d_in, const int* in_sizes, int n_in,
                              void* d_out, int out_size) {
    const float* x     = (const float*)d_in[0];
    const int*   ei    = (const int*)d_in[1];
    const int*   batch = (const int*)d_in[2];
    const float* W1 = (const float*)d_in[3];
    const float* b1 = (const float*)d_in[4];
    const float* W2 = (const float*)d_in[5];
    const float* b2 = (const float*)d_in[6];
    const float* W3 = (const float*)d_in[7];
    const float* b3 = (const float*)d_in[8];
    const float* lw = (const float*)d_in[9];
    const float* lb = (const float*)d_in[10];
    float* out = (float*)d_out;

    int N = in_sizes[0] / FIN;
    int E = in_sizes[1] / 2;
    int G = out_size;

    const int* src = ei;
    const int* dst = ei + E;

    int nb  = (N + SCAN_B - 1) / SCAN_B;
    int eb  = (E + 255) / 256;
    int wb  = (N * 32 + 255) / 256;
    int mb  = (N + 127) / 128;
    int inb = (N + 1) / 2;

    cudaFuncSetAttribute(k_gemm_mma, cudaFuncAttributeMaxDynamicSharedMemorySize, GEMM_SMEM);

    // ---- CSR build + bounds ----
    k_clear<<<nb, SCAN_B>>>(N, G);
    k_deg<<<eb, 256>>>(dst, E);
    k_scan1<<<nb, SCAN_B>>>(N);
    k_scan2<<<1, MAXBLK>>>(nb);
    k_scan3<<<(N + 256) / 256, 256>>>(batch, N, E);
    k_fill<<<eb, 256>>>(src, dst, E);

    // ---- layer 1: (Â X) W1 + b1 ----
    k_aggx<<<wb, 256>>>(x, N);
    k_gemm_in<<<inb, 256>>>(W1, b1, N);
    // ---- layer 2 ----
    k_gemm_mma<<<mb, 256, GEMM_SMEM>>>(W2, N);
    k_gather_h<<<wb, 256>>>(b2, N);
    // ---- layer 3 ----
    k_gemm_mma<<<mb, 256, GEMM_SMEM>>>(W3, N);
    k_gather_h<<<wb, 256>>>(b3, N);

    // ---- pool + linear ----
    k_pool<<<G, HDIM>>>(lw, lb, out);
}

// round 9
// speedup vs baseline: 1.2839x; 1.1401x over previous
#include <cuda_runtime.h>
#include <cuda_bf16.h>
#include <cstdint>

#define MAXN 100000
#define MAXE 1600000
#define HDIM 128
#define FIN  9
#define GMAX 256
#define SCAN_B 256
#define MAXBLK 512
#define KC   32                 // k per staging phase
#define AST  36                 // padded smem stride (36 mod 32 == 4 -> conflict-free frags)
#define GEMM_SMEM (4 * 128 * AST * 4)   // A_hi, A_lo, W_hi, W_lo = 73728 B -> 2 CTA/SM

// -------- scratch (device symbols only; NEVER pass from host — GB300 ATS trap) ----
__device__ __align__(128) float g_dinv[MAXN];
__device__ __align__(128) __nv_bfloat16 g_bufA16[MAXN * HDIM];  // pre-agg (bf16)
__device__ __align__(128) float g_bufB[MAXN * HDIM];            // layer output (fp32)
__device__ __align__(128) float g_xa[MAXN * FIN];
__device__ int   g_degc[MAXN];
__device__ int   g_rowstart[MAXN + 1];
__device__ int   g_cursor[MAXN];
__device__ int   g_bsum[MAXBLK];
__device__ int   g_boff[MAXBLK];
__device__ __align__(128) int2 g_cedge[MAXE];   // (src, norm-as-int)
__device__ int   g_lo[GMAX];
__device__ int   g_hi[GMAX];

__device__ __forceinline__ unsigned f2tf32(float f) {
    unsigned u;
    asm("cvt.rna.tf32.f32 %0, %1;" : "=r"(u) : "f"(f));
    return u;
}
__device__ __forceinline__ void tf32split(float f, unsigned& hi, unsigned& lo) {
    hi = f2tf32(f);
    float hif = __uint_as_float(hi);
    lo = f2tf32(f - hif);
}

// ======================= setup =======================
__global__ void k_clear(int n, int g) {
    int i = blockIdx.x * blockDim.x + threadIdx.x;
    if (i < n) g_degc[i] = 0;
    if (i < g) { g_lo[i] = 0; g_hi[i] = 0; }
}

// out[g] = lin_b (accumulation target for fused layer-3 pool)
__global__ void k_init_out(const float* __restrict__ lb, float* __restrict__ out, int g) {
    int i = blockIdx.x * blockDim.x + threadIdx.x;
    if (i < g) out[i] = lb[0];
}

__global__ void k_deg(const int* __restrict__ dst, int E) {
    int e = blockIdx.x * blockDim.x + threadIdx.x;
    if (e < E) atomicAdd(&g_degc[dst[e]], 1);
}

__global__ void k_scan1(int n) {
    __shared__ int sh[SCAN_B];
    int i = blockIdx.x * SCAN_B + threadIdx.x;
    int v = (i < n) ? g_degc[i] : 0;
    if (i < n) g_dinv[i] = rsqrtf((float)(v + 1));
    sh[threadIdx.x] = v;
    __syncthreads();
    for (int off = 1; off < SCAN_B; off <<= 1) {
        int t = (threadIdx.x >= (unsigned)off) ? sh[threadIdx.x - off] : 0;
        __syncthreads();
        sh[threadIdx.x] += t;
        __syncthreads();
    }
    if (i < n) g_rowstart[i] = sh[threadIdx.x] - v;
    if (threadIdx.x == SCAN_B - 1) g_bsum[blockIdx.x] = sh[SCAN_B - 1];
}

__global__ void k_scan2(int nb) {
    __shared__ int sh[MAXBLK];
    int v = (threadIdx.x < (unsigned)nb) ? g_bsum[threadIdx.x] : 0;
    sh[threadIdx.x] = v;
    __syncthreads();
    for (int off = 1; off < MAXBLK; off <<= 1) {
        int t = (threadIdx.x >= (unsigned)off) ? sh[threadIdx.x - off] : 0;
        __syncthreads();
        sh[threadIdx.x] += t;
        __syncthreads();
    }
    if (threadIdx.x < (unsigned)nb) g_boff[threadIdx.x] = sh[threadIdx.x] - v;
}

__global__ void k_scan3(const int* __restrict__ batch, int n, int E) {
    int i = blockIdx.x * blockDim.x + threadIdx.x;
    if (i < n) {
        int r = g_rowstart[i] + g_boff[i >> 8];
        g_rowstart[i] = r;
        g_cursor[i] = r;
        int b = batch[i];
        if (i == 0) g_lo[b] = 0;
        else {
            int pb = batch[i - 1];
            if (pb != b) { g_lo[b] = i; g_hi[pb] = i; }
        }
        if (i == n - 1) g_hi[b] = n;
    } else if (i == n) {
        g_rowstart[n] = E;
    }
}

__global__ void k_fill(const int* __restrict__ src, const int* __restrict__ dst, int E) {
    int e = blockIdx.x * blockDim.x + threadIdx.x;
    if (e >= E) return;
    int s = src[e], d = dst[e];
    int pos = atomicAdd(&g_cursor[d], 1);
    float nrm = g_dinv[s] * g_dinv[d];
    g_cedge[pos] = make_int2(s, __float_as_int(nrm));
}

// ======================= layer 1 =======================
__global__ void k_aggx(const float* __restrict__ x, int n) {
    int w = (blockIdx.x * blockDim.x + threadIdx.x) >> 5;
    if (w >= n) return;
    int lane = threadIdx.x & 31;
    int rs = g_rowstart[w], re = g_rowstart[w + 1];
    float di = g_dinv[w];
    float acc = 0.f;
    if (lane < FIN) acc = x[w * FIN + lane] * di * di;
    for (int j = rs; j < re; j++) {
        int2 e = g_cedge[j];
        float wt = __int_as_float(e.y);
        if (lane < FIN) acc += x[e.x * FIN + lane] * wt;
    }
    if (lane < FIN) g_xa[w * FIN + lane] = acc;
}

__global__ void k_gemm_in(const float* __restrict__ W, const float* __restrict__ bias, int n) {
    __shared__ float xr[2][FIN];
    int slot = threadIdx.x / HDIM;
    int node = blockIdx.x * 2 + slot;
    int c = threadIdx.x % HDIM;
    if (node < n && c < FIN) xr[slot][c] = g_xa[node * FIN + c];
    __syncthreads();
    if (node >= n) return;
    float s = bias[c];
#pragma unroll
    for (int k = 0; k < FIN; k++) s += xr[slot][k] * W[k * HDIM + c];
    g_bufB[node * HDIM + c] = s;
}

// =============== hidden GEMM: 3xTF32 warp-MMA, KC=32 phases (2 CTA/SM) =======
__global__ void __launch_bounds__(256) k_gemm_mma(const float* __restrict__ W, int n) {
    extern __shared__ unsigned smu[];
    unsigned* sAhi = smu;
    unsigned* sAlo = smu + 128 * AST;
    unsigned* sWhi = smu + 2 * 128 * AST;
    unsigned* sWlo = smu + 3 * 128 * AST;
    int tid = threadIdx.x;
    int node0 = blockIdx.x * 128;

    int wid = tid >> 5, lane = tid & 31;
    int m0 = wid * 16;
    int lr = lane >> 2;      // 0..7
    int lc = lane & 3;       // 0..3

    float d[16][4];
#pragma unroll
    for (int t = 0; t < 16; t++)
#pragma unroll
        for (int j = 0; j < 4; j++) d[t][j] = 0.f;

#pragma unroll 1
    for (int p = 0; p < 4; p++) {
        int k0 = p * KC;
        if (p) __syncthreads();   // protect smem reuse
        // stage A chunk: 128 rows x 32 k (relu + split); 16 elem/thread
        for (int idx = tid; idx < 128 * KC; idx += 256) {
            int r = idx >> 5, c = idx & (KC - 1);
            float v = 0.f;
            if (node0 + r < n) v = fmaxf(g_bufB[(node0 + r) * HDIM + k0 + c], 0.f);
            unsigned hi, lo; tf32split(v, hi, lo);
            sAhi[r * AST + c] = hi;
            sAlo[r * AST + c] = lo;
        }
        // stage W^T chunk: sW[nn][kl] = split(W[k0+kl][nn])
        for (int idx = tid; idx < KC * 128; idx += 256) {
            int kl = idx >> 7, nn = idx & 127;
            float v = __ldg(&W[(k0 + kl) * HDIM + nn]);
            unsigned hi, lo; tf32split(v, hi, lo);
            sWhi[nn * AST + kl] = hi;
            sWlo[nn * AST + kl] = lo;
        }
        __syncthreads();

        const unsigned* pah = &sAhi[(m0 + lr) * AST + lc];
        const unsigned* pal = &sAlo[(m0 + lr) * AST + lc];

#pragma unroll
        for (int kc = 0; kc < KC / 8; kc++) {
            int kb = kc * 8;
            unsigned ah0 = pah[kb],     ah1 = pah[8 * AST + kb];
            unsigned ah2 = pah[kb + 4], ah3 = pah[8 * AST + kb + 4];
            unsigned al0 = pal[kb],     al1 = pal[8 * AST + kb];
            unsigned al2 = pal[kb + 4], al3 = pal[8 * AST + kb + 4];
#pragma unroll
            for (int t = 0; t < 16; t++) {
                const unsigned* pbh = &sWhi[(t * 8 + lr) * AST + kb + lc];
                const unsigned* pbl = &sWlo[(t * 8 + lr) * AST + kb + lc];
                unsigned bh0 = pbh[0], bh1 = pbh[4];
                unsigned bl0 = pbl[0], bl1 = pbl[4];
                asm volatile(
                    "mma.sync.aligned.m16n8k8.row.col.f32.tf32.tf32.f32 "
                    "{%0,%1,%2,%3}, {%4,%5,%6,%7}, {%8,%9}, {%0,%1,%2,%3};"
                    : "+f"(d[t][0]), "+f"(d[t][1]), "+f"(d[t][2]), "+f"(d[t][3])
                    : "r"(ah0), "r"(ah1), "r"(ah2), "r"(ah3), "r"(bh0), "r"(bh1));
                asm volatile(
                    "mma.sync.aligned.m16n8k8.row.col.f32.tf32.tf32.f32 "
                    "{%0,%1,%2,%3}, {%4,%5,%6,%7}, {%8,%9}, {%0,%1,%2,%3};"
                    : "+f"(d[t][0]), "+f"(d[t][1]), "+f"(d[t][2]), "+f"(d[t][3])
                    : "r"(ah0), "r"(ah1), "r"(ah2), "r"(ah3), "r"(bl0), "r"(bl1));
                asm volatile(
                    "mma.sync.aligned.m16n8k8.row.col.f32.tf32.tf32.f32 "
                    "{%0,%1,%2,%3}, {%4,%5,%6,%7}, {%8,%9}, {%0,%1,%2,%3};"
                    : "+f"(d[t][0]), "+f"(d[t][1]), "+f"(d[t][2]), "+f"(d[t][3])
                    : "r"(al0), "r"(al1), "r"(al2), "r"(al3), "r"(bh0), "r"(bh1));
            }
        }
    }

    // epilogue: bf16 pairs. D rows m0+lr (+8), cols t*8 + 2*lc (+1).
    int row0 = node0 + m0 + lr;
    int row1 = row0 + 8;
#pragma unroll
    for (int t = 0; t < 16; t++) {
        int col = t * 8 + lc * 2;
        if (row0 < n) {
            __nv_bfloat162 pp = __floats2bfloat162_rn(d[t][0], d[t][1]);
            *reinterpret_cast<unsigned*>(&g_bufA16[row0 * HDIM + col]) =
                *reinterpret_cast<unsigned*>(&pp);
        }
        if (row1 < n) {
            __nv_bfloat162 pp = __floats2bfloat162_rn(d[t][2], d[t][3]);
            *reinterpret_cast<unsigned*>(&g_bufA16[row1 * HDIM + col]) =
                *reinterpret_cast<unsigned*>(&pp);
        }
    }
}

// ======================= hidden aggregate =======================
__device__ __forceinline__ float4 ld_row4(int node, int q) {
    uint2 raw = *reinterpret_cast<const uint2*>(&g_bufA16[node * HDIM + q]);
    __nv_bfloat162 p0 = *reinterpret_cast<__nv_bfloat162*>(&raw.x);
    __nv_bfloat162 p1 = *reinterpret_cast<__nv_bfloat162*>(&raw.y);
    float2 f0 = __bfloat1622float2(p0);
    float2 f1 = __bfloat1622float2(p1);
    return make_float4(f0.x, f0.y, f1.x, f1.y);
}

// shared gather core: returns aggregated row slice (incl. self-loop + bias)
__device__ __forceinline__ float4 gather_row(int w, int q, const float* bias) {
    int rs = g_rowstart[w], re = g_rowstart[w + 1];
    float di = g_dinv[w];
    float4 self = ld_row4(w, q);
    float d2 = di * di;
    float4 acc = make_float4(self.x * d2, self.y * d2, self.z * d2, self.w * d2);

    int j = rs;
    for (; j + 7 < re; j += 8) {   // 8-deep MLP
        int2 e0 = g_cedge[j],     e1 = g_cedge[j + 1];
        int2 e2 = g_cedge[j + 2], e3 = g_cedge[j + 3];
        int2 e4 = g_cedge[j + 4], e5 = g_cedge[j + 5];
        int2 e6 = g_cedge[j + 6], e7 = g_cedge[j + 7];
        float4 v0 = ld_row4(e0.x, q), v1 = ld_row4(e1.x, q);
        float4 v2 = ld_row4(e2.x, q), v3 = ld_row4(e3.x, q);
        float4 v4 = ld_row4(e4.x, q), v5 = ld_row4(e5.x, q);
        float4 v6 = ld_row4(e6.x, q), v7 = ld_row4(e7.x, q);
        float w0 = __int_as_float(e0.y), w1 = __int_as_float(e1.y);
        float w2 = __int_as_float(e2.y), w3 = __int_as_float(e3.y);
        float w4 = __int_as_float(e4.y), w5 = __int_as_float(e5.y);
        float w6 = __int_as_float(e6.y), w7 = __int_as_float(e7.y);
        acc.x += v0.x*w0 + v1.x*w1 + v2.x*w2 + v3.x*w3 + v4.x*w4 + v5.x*w5 + v6.x*w6 + v7.x*w7;
        acc.y += v0.y*w0 + v1.y*w1 + v2.y*w2 + v3.y*w3 + v4.y*w4 + v5.y*w5 + v6.y*w6 + v7.y*w7;
        acc.z += v0.z*w0 + v1.z*w1 + v2.z*w2 + v3.z*w3 + v4.z*w4 + v5.z*w5 + v6.z*w6 + v7.z*w7;
        acc.w += v0.w*w0 + v1.w*w1 + v2.w*w2 + v3.w*w3 + v4.w*w4 + v5.w*w5 + v6.w*w6 + v7.w*w7;
    }
    for (; j < re; j++) {
        int2 e = g_cedge[j];
        float wt = __int_as_float(e.y);
        float4 v = ld_row4(e.x, q);
        acc.x += v.x * wt; acc.y += v.y * wt; acc.z += v.z * wt; acc.w += v.w * wt;
    }
    float4 b = __ldg(reinterpret_cast<const float4*>(&bias[q]));
    acc.x += b.x; acc.y += b.y; acc.z += b.z; acc.w += b.w;
    return acc;
}

// layer-2 aggregate: writes bufB
__global__ void k_gather_h(const float* __restrict__ bias, int n) {
    int w = (blockIdx.x * blockDim.x + threadIdx.x) >> 5;
    if (w >= n) return;
    int q = (threadIdx.x & 31) * 4;
    float4 acc = gather_row(w, q, bias);
    *reinterpret_cast<float4*>(&g_bufB[w * HDIM + q]) = acc;
}

// layer-3 aggregate fused with mean-pool + final linear:
// out[g] += dot(h3_row, lin_w) / cnt[g]   (out pre-initialized to lin_b)
__global__ void k_gather_pool(const float* __restrict__ bias,
                              const float* __restrict__ lin_w,
                              const int* __restrict__ batch,
                              float* __restrict__ out, int n) {
    int w = (blockIdx.x * blockDim.x + threadIdx.x) >> 5;
    if (w >= n) return;
    int lane = threadIdx.x & 31;
    int q = lane * 4;
    float4 acc = gather_row(w, q, bias);
    float4 lw4 = __ldg(reinterpret_cast<const float4*>(&lin_w[q]));
    float v = acc.x * lw4.x + acc.y * lw4.y + acc.z * lw4.z + acc.w * lw4.w;
#pragma unroll
    for (int off = 16; off > 0; off >>= 1)
        v += __shfl_down_sync(0xffffffffu, v, off);
    if (lane == 0) {
        int b = batch[w];
        float inv = 1.f / (float)(g_hi[b] - g_lo[b]);
        asm volatile("red.global.add.f32 [%0], %1;" :: "l"(&out[b]), "f"(v * inv) : "memory");
    }
}

extern "C" void kernel_launch(void* const* d_in, const int* in_sizes, int n_in,
                              void* d_out, int out_size) {
    const float* x     = (const float*)d_in[0];
    const int*   ei    = (const int*)d_in[1];
    const int*   batch = (const int*)d_in[2];
    const float* W1 = (const float*)d_in[3];
    const float* b1 = (const float*)d_in[4];
    const float* W2 = (const float*)d_in[5];
    const float* b2 = (const float*)d_in[6];
    const float* W3 = (const float*)d_in[7];
    const float* b3 = (const float*)d_in[8];
    const float* lw = (const float*)d_in[9];
    const float* lb = (const float*)d_in[10];
    float* out = (float*)d_out;

    int N = in_sizes[0] / FIN;
    int E = in_sizes[1] / 2;
    int G = out_size;

    const int* src = ei;
    const int* dst = ei + E;

    int nb  = (N + SCAN_B - 1) / SCAN_B;
    int eb  = (E + 255) / 256;
    int wb  = (N * 32 + 255) / 256;
    int mb  = (N + 127) / 128;
    int inb = (N + 1) / 2;

    cudaFuncSetAttribute(k_gemm_mma, cudaFuncAttributeMaxDynamicSharedMemorySize, GEMM_SMEM);

    // ---- CSR build + bounds ----
    k_clear<<<nb, SCAN_B>>>(N, G);
    k_init_out<<<1, 256>>>(lb, out, G);
    k_deg<<<eb, 256>>>(dst, E);
    k_scan1<<<nb, SCAN_B>>>(N);
    k_scan2<<<1, MAXBLK>>>(nb);
    k_scan3<<<(N + 256) / 256, 256>>>(batch, N, E);
    k_fill<<<eb, 256>>>(src, dst, E);

    // ---- layer 1: (Â X) W1 + b1 ----
    k_aggx<<<wb, 256>>>(x, N);
    k_gemm_in<<<inb, 256>>>(W1, b1, N);
    // ---- layer 2 ----
    k_gemm_mma<<<mb, 256, GEMM_SMEM>>>(W2, N);
    k_gather_h<<<wb, 256>>>(b2, N);
    // ---- layer 3 (gather fused with pool + linear) ----
    k_gemm_mma<<<mb, 256, GEMM_SMEM>>>(W3, N);
    k_gather_pool<<<wb, 256>>>(b3, lw, batch, out, N);
}